// round 7
// baseline (speedup 1.0000x reference)
#include <cuda_runtime.h>
#include <cuda_bf16.h>

// Problem constants
#define BATCH 16
#define SEQ   1024
#define F     256
#define MROWS (BATCH * SEQ)   // 16384

// Tiling
#define BM 64
#define BN 64
#define BK 16

// -------- scratch (no allocation allowed; __device__ globals) --------
__device__ float g_alpha[MROWS * F];
__device__ float g_beta [MROWS * F];
__device__ float g_unary[MROWS * F];
__device__ float g_att  [MROWS * F];
__device__ float g_M    [BATCH * F * F];
__device__ float g_d    [MROWS];

// FMA micro-kernel body shared by all GEMMs (4x4 per thread)
#define MICRO_FMA(As_, Bs_)                                                  \
    _Pragma("unroll")                                                        \
    for (int kk = 0; kk < BK; ++kk) {                                        \
        float4 av = *(const float4*)&As_[kk][ty * 4];                        \
        float4 bv = *(const float4*)&Bs_[kk][tx * 4];                        \
        acc[0][0] += av.x * bv.x; acc[0][1] += av.x * bv.y;                  \
        acc[0][2] += av.x * bv.z; acc[0][3] += av.x * bv.w;                  \
        acc[1][0] += av.y * bv.x; acc[1][1] += av.y * bv.y;                  \
        acc[1][2] += av.y * bv.z; acc[1][3] += av.y * bv.w;                  \
        acc[2][0] += av.z * bv.x; acc[2][1] += av.z * bv.y;                  \
        acc[2][2] += av.z * bv.z; acc[2][3] += av.z * bv.w;                  \
        acc[3][0] += av.w * bv.x; acc[3][1] += av.w * bv.y;                  \
        acc[3][2] += av.w * bv.z; acc[3][3] += av.w * bv.w;                  \
    }

// ============================================================================
// Kernel 1: NT GEMM x [16384,256] @ W^T [256,256] for three weight matrices.
//   out[m,g] = sum_k X[m,k] * W[g,k]   (+ bias for the "unary" matrix)
// grid: (4, 256, 3). Register-prefetch double buffered.
// ============================================================================
__global__ __launch_bounds__(256) void gemm_nt_3(
    const float* __restrict__ X,
    const float* __restrict__ W0,
    const float* __restrict__ W1,
    const float* __restrict__ W2,
    const float* __restrict__ bias)
{
    const int z = blockIdx.z;
    const float* __restrict__ W = (z == 0) ? W0 : (z == 1) ? W1 : W2;
    float* __restrict__ O = (z == 0) ? g_alpha : (z == 1) ? g_beta : g_unary;

    __shared__ float As[BK][BM + 4];
    __shared__ float Bs[BK][BN + 4];

    const int tid = threadIdx.x;
    const int m0 = blockIdx.y * BM;
    const int n0 = blockIdx.x * BN;

    const int lr = tid >> 2;          // 0..63
    const int lc = (tid & 3) * 4;     // 0,4,8,12
    const int tx = tid & 15;
    const int ty = tid >> 4;

    float acc[4][4] = {};

    const float* pa = &X[(m0 + lr) * F + lc];
    const float* pb = &W[(n0 + lr) * F + lc];

    float4 a = *(const float4*)pa;
    float4 b = *(const float4*)pb;

    for (int k0 = 0; k0 < F; k0 += BK) {
        As[lc + 0][lr] = a.x; As[lc + 1][lr] = a.y;
        As[lc + 2][lr] = a.z; As[lc + 3][lr] = a.w;
        Bs[lc + 0][lr] = b.x; Bs[lc + 1][lr] = b.y;
        Bs[lc + 2][lr] = b.z; Bs[lc + 3][lr] = b.w;
        __syncthreads();
        if (k0 + BK < F) {
            a = *(const float4*)(pa + k0 + BK);
            b = *(const float4*)(pb + k0 + BK);
        }
        MICRO_FMA(As, Bs)
        __syncthreads();
    }

    float4 bv = make_float4(0.f, 0.f, 0.f, 0.f);
    if (z == 2) bv = *(const float4*)&bias[n0 + tx * 4];
#pragma unroll
    for (int i = 0; i < 4; ++i) {
        int row = m0 + ty * 4 + i;
        float4 o;
        o.x = acc[i][0] + bv.x; o.y = acc[i][1] + bv.y;
        o.z = acc[i][2] + bv.z; o.w = acc[i][3] + bv.w;
        *(float4*)&O[row * F + n0 + tx * 4] = o;
    }
}

// ============================================================================
// Kernel 2: per-row dot  d[m] = alpha[m,:] . beta[m,:]   (one warp per row)
// ============================================================================
__global__ __launch_bounds__(256) void dot_ab()
{
    int row = blockIdx.x * 8 + (threadIdx.x >> 5);
    int lane = threadIdx.x & 31;
    const float4* a = (const float4*)&g_alpha[row * F];
    const float4* b = (const float4*)&g_beta[row * F];
    float s = 0.f;
#pragma unroll
    for (int i = lane; i < F / 4; i += 32) {
        float4 av = a[i], bv = b[i];
        s += av.x * bv.x + av.y * bv.y + av.z * bv.z + av.w * bv.w;
    }
#pragma unroll
    for (int off = 16; off > 0; off >>= 1)
        s += __shfl_xor_sync(0xffffffffu, s, off);
    if (lane == 0) g_d[row] = s;
}

// ============================================================================
// Kernel 3: TN GEMM per batch  M[b][h][f] = sum_n beta[b,n,h] * unary[b,n,f]
// grid: (4, 4, 16). K loop over SEQ=1024 — prefetch matters most here.
// ============================================================================
__global__ __launch_bounds__(256) void gemm_tn_M()
{
    const int b = blockIdx.z;
    const float* __restrict__ A  = g_beta  + b * SEQ * F;
    const float* __restrict__ Bp = g_unary + b * SEQ * F;
    float* __restrict__ O = g_M + b * F * F;

    __shared__ float As[BK][BM + 4];
    __shared__ float Bs[BK][BN + 4];

    const int tid = threadIdx.x;
    const int m0 = blockIdx.y * BM;
    const int n0 = blockIdx.x * BN;

    const int lr = tid >> 4;          // k row 0..15
    const int lc = (tid & 15) * 4;    // col 0..60
    const int tx = tid & 15;
    const int ty = tid >> 4;

    float acc[4][4] = {};

    const float* pa = &A [lr * F + m0 + lc];
    const float* pb = &Bp[lr * F + n0 + lc];

    float4 a  = *(const float4*)pa;
    float4 b4 = *(const float4*)pb;

    for (int k0 = 0; k0 < SEQ; k0 += BK) {
        *(float4*)&As[lr][lc] = a;
        *(float4*)&Bs[lr][lc] = b4;
        __syncthreads();
        if (k0 + BK < SEQ) {
            a  = *(const float4*)(pa + (k0 + BK) * F);
            b4 = *(const float4*)(pb + (k0 + BK) * F);
        }
        MICRO_FMA(As, Bs)
        __syncthreads();
    }

#pragma unroll
    for (int i = 0; i < 4; ++i) {
        int row = m0 + ty * 4 + i;
        float4 o;
        o.x = acc[i][0]; o.y = acc[i][1]; o.z = acc[i][2]; o.w = acc[i][3];
        *(float4*)&O[row * F + n0 + tx * 4] = o;
    }
}

// ============================================================================
// Kernel 4: NN GEMM  att[m,f] = (sum_h alpha[m,h]*M[b][h][f] - d[m]*unary[m,f])/SEQ
// grid: (4, 256)
// ============================================================================
__global__ __launch_bounds__(256) void gemm_nn_att()
{
    const int m0 = blockIdx.y * BM;
    const int n0 = blockIdx.x * BN;
    const int b = m0 >> 10;  // / SEQ (BM divides SEQ)
    const float* __restrict__ A  = g_alpha;
    const float* __restrict__ Bm = g_M + b * F * F;

    __shared__ float As[BK][BM + 4];
    __shared__ float Bs[BK][BN + 4];

    const int tid = threadIdx.x;
    const int lrA = tid >> 2;          // 0..63
    const int lcA = (tid & 3) * 4;     // 0,4,8,12
    const int lrB = tid >> 4;          // 0..15
    const int lcB = (tid & 15) * 4;    // 0..60
    const int tx = tid & 15;
    const int ty = tid >> 4;

    float acc[4][4] = {};

    const float* pa = &A [(m0 + lrA) * F + lcA];
    const float* pb = &Bm[lrB * F + n0 + lcB];

    float4 a  = *(const float4*)pa;
    float4 b4 = *(const float4*)pb;

    for (int k0 = 0; k0 < F; k0 += BK) {
        As[lcA + 0][lrA] = a.x; As[lcA + 1][lrA] = a.y;
        As[lcA + 2][lrA] = a.z; As[lcA + 3][lrA] = a.w;
        *(float4*)&Bs[lrB][lcB] = b4;
        __syncthreads();
        if (k0 + BK < F) {
            a  = *(const float4*)(pa + k0 + BK);
            b4 = *(const float4*)(pb + (k0 + BK) * F);
        }
        MICRO_FMA(As, Bs)
        __syncthreads();
    }

    const float invN = 1.0f / (float)SEQ;
#pragma unroll
    for (int i = 0; i < 4; ++i) {
        int row = m0 + ty * 4 + i;
        float dv = g_d[row];
        float4 u = *(const float4*)&g_unary[row * F + n0 + tx * 4];
        float4 o;
        o.x = (acc[i][0] - dv * u.x) * invN;
        o.y = (acc[i][1] - dv * u.y) * invN;
        o.z = (acc[i][2] - dv * u.z) * invN;
        o.w = (acc[i][3] - dv * u.w) * invN;
        *(float4*)&g_att[row * F + n0 + tx * 4] = o;
    }
}

// ============================================================================
// Kernel 5: NT GEMM + residual  out[m,g] = sum_f att[m,f]*W_r[g,f] + x[m,g]
// grid: (4, 256)
// ============================================================================
__global__ __launch_bounds__(256) void gemm_nt_out(
    const float* __restrict__ Wr,
    const float* __restrict__ X,
    float* __restrict__ out)
{
    __shared__ float As[BK][BM + 4];
    __shared__ float Bs[BK][BN + 4];

    const int tid = threadIdx.x;
    const int m0 = blockIdx.y * BM;
    const int n0 = blockIdx.x * BN;

    const int lr = tid >> 2;
    const int lc = (tid & 3) * 4;
    const int tx = tid & 15;
    const int ty = tid >> 4;

    float acc[4][4] = {};

    const float* pa = &g_att[(m0 + lr) * F + lc];
    const float* pb = &Wr   [(n0 + lr) * F + lc];

    float4 a = *(const float4*)pa;
    float4 b = *(const float4*)pb;

    for (int k0 = 0; k0 < F; k0 += BK) {
        As[lc + 0][lr] = a.x; As[lc + 1][lr] = a.y;
        As[lc + 2][lr] = a.z; As[lc + 3][lr] = a.w;
        Bs[lc + 0][lr] = b.x; Bs[lc + 1][lr] = b.y;
        Bs[lc + 2][lr] = b.z; Bs[lc + 3][lr] = b.w;
        __syncthreads();
        if (k0 + BK < F) {
            a = *(const float4*)(pa + k0 + BK);
            b = *(const float4*)(pb + k0 + BK);
        }
        MICRO_FMA(As, Bs)
        __syncthreads();
    }

#pragma unroll
    for (int i = 0; i < 4; ++i) {
        int row = m0 + ty * 4 + i;
        float4 xr = *(const float4*)&X[row * F + n0 + tx * 4];
        float4 o;
        o.x = acc[i][0] + xr.x; o.y = acc[i][1] + xr.y;
        o.z = acc[i][2] + xr.z; o.w = acc[i][3] + xr.w;
        *(float4*)&out[row * F + n0 + tx * 4] = o;
    }
}

// ============================================================================
// Launch
// ============================================================================
extern "C" void kernel_launch(void* const* d_in, const int* in_sizes, int n_in,
                              void* d_out, int out_size)
{
    const float* x  = (const float*)d_in[0];
    const float* Wa = (const float*)d_in[1];
    const float* Wb = (const float*)d_in[2];
    const float* Wu = (const float*)d_in[3];
    const float* bu = (const float*)d_in[4];
    const float* Wr = (const float*)d_in[5];
    float* out = (float*)d_out;

    dim3 t(256);
    gemm_nt_3  <<<dim3(F / BN, MROWS / BM, 3), t>>>(x, Wa, Wb, Wu, bu);
    dot_ab     <<<MROWS / 8, 256>>>();
    gemm_tn_M  <<<dim3(F / BN, F / BM, BATCH), t>>>();
    gemm_nn_att<<<dim3(F / BN, MROWS / BM), t>>>();
    gemm_nt_out<<<dim3(F / BN, MROWS / BM), t>>>(Wr, x, out);
}

// round 9
// speedup vs baseline: 1.1977x; 1.1977x over previous
#include <cuda_runtime.h>
#include <cuda_bf16.h>

// Problem constants
#define BATCH 16
#define SEQ   1024
#define F     256
#define MROWS (BATCH * SEQ)   // 16384

// Small-tile params (kept for gemm_tn_M)
#define BM 64
#define BN 64
#define BK 16

// Big-tile params
#define TBM 128
#define TBN 128
#define TBK 8
#define SPAD 4   // smem row padding (floats)

// -------- scratch (no allocation allowed; __device__ globals) --------
__device__ float g_alpha[MROWS * F];
__device__ float g_beta [MROWS * F];
__device__ float g_unary[MROWS * F];
__device__ float g_att  [MROWS * F];
__device__ float g_M    [BATCH * F * F];
__device__ float g_d    [MROWS];

// ---------------- 8x8 micro-kernel over 128-wide smem tiles ----------------
// Fragments are split 4+4 (offsets ty*4 and 64+ty*4) so every LDS.128 is
// stride-16B across the warp -> conflict-free.
#define MICRO8(As_, Bs_)                                                     \
    _Pragma("unroll")                                                        \
    for (int kk = 0; kk < TBK; ++kk) {                                       \
        float4 a0 = *(const float4*)&As_[kk][ty * 4];                        \
        float4 a1 = *(const float4*)&As_[kk][64 + ty * 4];                   \
        float4 b0 = *(const float4*)&Bs_[kk][tx * 4];                        \
        float4 b1 = *(const float4*)&Bs_[kk][64 + tx * 4];                   \
        float av[8] = {a0.x, a0.y, a0.z, a0.w, a1.x, a1.y, a1.z, a1.w};      \
        float bv[8] = {b0.x, b0.y, b0.z, b0.w, b1.x, b1.y, b1.z, b1.w};      \
        _Pragma("unroll")                                                    \
        for (int i = 0; i < 8; ++i)                                          \
            _Pragma("unroll")                                                \
            for (int j = 0; j < 8; ++j)                                      \
                acc[i][j] += av[i] * bv[j];                                  \
    }

// row index for micro-tile row i (0..7)
#define MROW(i) (m0 + ((i) < 4 ? ty * 4 + (i) : 64 + ty * 4 + (i) - 4))

// ============================================================================
// Kernel 1: NT GEMM x [16384,256] @ W^T for three weight matrices.
//   O[m,g] = sum_k X[m,k] * W[g,k]   (+ bias for z==2)
// grid: (2, 128, 3), 256 threads, 128x128x8 tiles.
// ============================================================================
__global__ __launch_bounds__(256) void gemm_nt_3(
    const float* __restrict__ X,
    const float* __restrict__ W0,
    const float* __restrict__ W1,
    const float* __restrict__ W2,
    const float* __restrict__ bias)
{
    const int z = blockIdx.z;
    const float* __restrict__ W = (z == 0) ? W0 : (z == 1) ? W1 : W2;
    float* __restrict__ O = (z == 0) ? g_alpha : (z == 1) ? g_beta : g_unary;

    __shared__ float As[TBK][TBM + SPAD];
    __shared__ float Bs[TBK][TBN + SPAD];

    const int tid = threadIdx.x;
    const int m0 = blockIdx.y * TBM;
    const int n0 = blockIdx.x * TBN;

    const int lr = tid >> 1;          // 0..127  (row within tile)
    const int lc = (tid & 1) * 4;     // 0 or 4  (k offset)
    const int tx = tid & 15;
    const int ty = tid >> 4;

    float acc[8][8] = {};

    const float* pa = &X[(m0 + lr) * F + lc];
    const float* pb = &W[(n0 + lr) * F + lc];

    float4 a = *(const float4*)pa;
    float4 b = *(const float4*)pb;

    for (int k0 = 0; k0 < F; k0 += TBK) {
        As[lc + 0][lr] = a.x; As[lc + 1][lr] = a.y;
        As[lc + 2][lr] = a.z; As[lc + 3][lr] = a.w;
        Bs[lc + 0][lr] = b.x; Bs[lc + 1][lr] = b.y;
        Bs[lc + 2][lr] = b.z; Bs[lc + 3][lr] = b.w;
        __syncthreads();
        if (k0 + TBK < F) {
            a = *(const float4*)(pa + k0 + TBK);
            b = *(const float4*)(pb + k0 + TBK);
        }
        MICRO8(As, Bs)
        __syncthreads();
    }

    float4 bv0 = make_float4(0.f, 0.f, 0.f, 0.f);
    float4 bv1 = bv0;
    if (z == 2) {
        bv0 = *(const float4*)&bias[n0 + tx * 4];
        bv1 = *(const float4*)&bias[n0 + 64 + tx * 4];
    }
#pragma unroll
    for (int i = 0; i < 8; ++i) {
        int row = MROW(i);
        float4 o0, o1;
        o0.x = acc[i][0] + bv0.x; o0.y = acc[i][1] + bv0.y;
        o0.z = acc[i][2] + bv0.z; o0.w = acc[i][3] + bv0.w;
        o1.x = acc[i][4] + bv1.x; o1.y = acc[i][5] + bv1.y;
        o1.z = acc[i][6] + bv1.z; o1.w = acc[i][7] + bv1.w;
        *(float4*)&O[row * F + n0 + tx * 4]      = o0;
        *(float4*)&O[row * F + n0 + 64 + tx * 4] = o1;
    }
}

// ============================================================================
// Kernel 2: per-row dot  d[m] = alpha[m,:] . beta[m,:]   (one warp per row)
// ============================================================================
__global__ __launch_bounds__(256) void dot_ab()
{
    int row = blockIdx.x * 8 + (threadIdx.x >> 5);
    int lane = threadIdx.x & 31;
    const float4* a = (const float4*)&g_alpha[row * F];
    const float4* b = (const float4*)&g_beta[row * F];
    float s = 0.f;
#pragma unroll
    for (int i = lane; i < F / 4; i += 32) {
        float4 av = a[i], bv = b[i];
        s += av.x * bv.x + av.y * bv.y + av.z * bv.z + av.w * bv.w;
    }
#pragma unroll
    for (int off = 16; off > 0; off >>= 1)
        s += __shfl_xor_sync(0xffffffffu, s, off);
    if (lane == 0) g_d[row] = s;
}

// ============================================================================
// Kernel 3: TN GEMM per batch  M[b][h][f] = sum_n beta[b,n,h] * unary[b,n,f]
// grid: (4, 4, 16). 64x64x16 tiles, 4x4 micro (output is small).
// ============================================================================
__global__ __launch_bounds__(256) void gemm_tn_M()
{
    const int b = blockIdx.z;
    const float* __restrict__ A  = g_beta  + b * SEQ * F;
    const float* __restrict__ Bp = g_unary + b * SEQ * F;
    float* __restrict__ O = g_M + b * F * F;

    __shared__ float As[BK][BM + 4];
    __shared__ float Bs[BK][BN + 4];

    const int tid = threadIdx.x;
    const int m0 = blockIdx.y * BM;
    const int n0 = blockIdx.x * BN;

    const int lr = tid >> 4;          // k row 0..15
    const int lc = (tid & 15) * 4;    // col 0..60
    const int tx = tid & 15;
    const int ty = tid >> 4;

    float acc[4][4] = {};

    const float* pa = &A [lr * F + m0 + lc];
    const float* pb = &Bp[lr * F + n0 + lc];

    float4 a  = *(const float4*)pa;
    float4 b4 = *(const float4*)pb;

    for (int k0 = 0; k0 < SEQ; k0 += BK) {
        *(float4*)&As[lr][lc] = a;
        *(float4*)&Bs[lr][lc] = b4;
        __syncthreads();
        if (k0 + BK < SEQ) {
            a  = *(const float4*)(pa + (k0 + BK) * F);
            b4 = *(const float4*)(pb + (k0 + BK) * F);
        }
#pragma unroll
        for (int kk = 0; kk < BK; ++kk) {
            float4 av = *(const float4*)&As[kk][ty * 4];
            float4 bv = *(const float4*)&Bs[kk][tx * 4];
            acc[0][0] += av.x * bv.x; acc[0][1] += av.x * bv.y;
            acc[0][2] += av.x * bv.z; acc[0][3] += av.x * bv.w;
            acc[1][0] += av.y * bv.x; acc[1][1] += av.y * bv.y;
            acc[1][2] += av.y * bv.z; acc[1][3] += av.y * bv.w;
            acc[2][0] += av.z * bv.x; acc[2][1] += av.z * bv.y;
            acc[2][2] += av.z * bv.z; acc[2][3] += av.z * bv.w;
            acc[3][0] += av.w * bv.x; acc[3][1] += av.w * bv.y;
            acc[3][2] += av.w * bv.z; acc[3][3] += av.w * bv.w;
        }
        __syncthreads();
    }

#pragma unroll
    for (int i = 0; i < 4; ++i) {
        int row = m0 + ty * 4 + i;
        float4 o;
        o.x = acc[i][0]; o.y = acc[i][1]; o.z = acc[i][2]; o.w = acc[i][3];
        *(float4*)&O[row * F + n0 + tx * 4] = o;
    }
}

// ============================================================================
// Kernel 4: NN GEMM  att[m,f] = (sum_h alpha[m,h]*M[b][h][f] - d[m]*unary[m,f])/SEQ
// grid: (2, 128), 128x128x8 tiles.
// ============================================================================
__global__ __launch_bounds__(256) void gemm_nn_att()
{
    const int m0 = blockIdx.y * TBM;
    const int n0 = blockIdx.x * TBN;
    const int b = m0 >> 10;  // / SEQ
    const float* __restrict__ A  = g_alpha;
    const float* __restrict__ Bm = g_M + b * F * F;

    __shared__ float As[TBK][TBM + SPAD];
    __shared__ float Bs[TBK][TBN + SPAD];

    const int tid = threadIdx.x;
    // A loader (transposed store): lrA 0..127, lcA 0/4
    const int lrA = tid >> 1;
    const int lcA = (tid & 1) * 4;
    // B loader (direct): lrB k-row 0..7, lcB col 0..124
    const int lrB = tid >> 5;
    const int lcB = (tid & 31) * 4;
    const int tx = tid & 15;
    const int ty = tid >> 4;

    float acc[8][8] = {};

    const float* pa = &A [(m0 + lrA) * F + lcA];
    const float* pb = &Bm[lrB * F + n0 + lcB];

    float4 a  = *(const float4*)pa;
    float4 b4 = *(const float4*)pb;

    for (int k0 = 0; k0 < F; k0 += TBK) {
        As[lcA + 0][lrA] = a.x; As[lcA + 1][lrA] = a.y;
        As[lcA + 2][lrA] = a.z; As[lcA + 3][lrA] = a.w;
        *(float4*)&Bs[lrB][lcB] = b4;
        __syncthreads();
        if (k0 + TBK < F) {
            a  = *(const float4*)(pa + k0 + TBK);
            b4 = *(const float4*)(pb + (k0 + TBK) * F);
        }
        MICRO8(As, Bs)
        __syncthreads();
    }

    const float invN = 1.0f / (float)SEQ;
#pragma unroll
    for (int i = 0; i < 8; ++i) {
        int row = MROW(i);
        float dv = g_d[row];
        float4 u0 = *(const float4*)&g_unary[row * F + n0 + tx * 4];
        float4 u1 = *(const float4*)&g_unary[row * F + n0 + 64 + tx * 4];
        float4 o0, o1;
        o0.x = (acc[i][0] - dv * u0.x) * invN;
        o0.y = (acc[i][1] - dv * u0.y) * invN;
        o0.z = (acc[i][2] - dv * u0.z) * invN;
        o0.w = (acc[i][3] - dv * u0.w) * invN;
        o1.x = (acc[i][4] - dv * u1.x) * invN;
        o1.y = (acc[i][5] - dv * u1.y) * invN;
        o1.z = (acc[i][6] - dv * u1.z) * invN;
        o1.w = (acc[i][7] - dv * u1.w) * invN;
        *(float4*)&g_att[row * F + n0 + tx * 4]      = o0;
        *(float4*)&g_att[row * F + n0 + 64 + tx * 4] = o1;
    }
}

// ============================================================================
// Kernel 5: NT GEMM + residual  out[m,g] = sum_f att[m,f]*W_r[g,f] + x[m,g]
// grid: (2, 128), 128x128x8 tiles.
// ============================================================================
__global__ __launch_bounds__(256) void gemm_nt_out(
    const float* __restrict__ Wr,
    const float* __restrict__ X,
    float* __restrict__ out)
{
    __shared__ float As[TBK][TBM + SPAD];
    __shared__ float Bs[TBK][TBN + SPAD];

    const int tid = threadIdx.x;
    const int m0 = blockIdx.y * TBM;
    const int n0 = blockIdx.x * TBN;

    const int lr = tid >> 1;
    const int lc = (tid & 1) * 4;
    const int tx = tid & 15;
    const int ty = tid >> 4;

    float acc[8][8] = {};

    const float* pa = &g_att[(m0 + lr) * F + lc];
    const float* pb = &Wr   [(n0 + lr) * F + lc];

    float4 a = *(const float4*)pa;
    float4 b = *(const float4*)pb;

    for (int k0 = 0; k0 < F; k0 += TBK) {
        As[lc + 0][lr] = a.x; As[lc + 1][lr] = a.y;
        As[lc + 2][lr] = a.z; As[lc + 3][lr] = a.w;
        Bs[lc + 0][lr] = b.x; Bs[lc + 1][lr] = b.y;
        Bs[lc + 2][lr] = b.z; Bs[lc + 3][lr] = b.w;
        __syncthreads();
        if (k0 + TBK < F) {
            a = *(const float4*)(pa + k0 + TBK);
            b = *(const float4*)(pb + k0 + TBK);
        }
        MICRO8(As, Bs)
        __syncthreads();
    }

#pragma unroll
    for (int i = 0; i < 8; ++i) {
        int row = MROW(i);
        float4 x0 = *(const float4*)&X[row * F + n0 + tx * 4];
        float4 x1 = *(const float4*)&X[row * F + n0 + 64 + tx * 4];
        float4 o0, o1;
        o0.x = acc[i][0] + x0.x; o0.y = acc[i][1] + x0.y;
        o0.z = acc[i][2] + x0.z; o0.w = acc[i][3] + x0.w;
        o1.x = acc[i][4] + x1.x; o1.y = acc[i][5] + x1.y;
        o1.z = acc[i][6] + x1.z; o1.w = acc[i][7] + x1.w;
        *(float4*)&out[row * F + n0 + tx * 4]      = o0;
        *(float4*)&out[row * F + n0 + 64 + tx * 4] = o1;
    }
}

// ============================================================================
// Launch
// ============================================================================
extern "C" void kernel_launch(void* const* d_in, const int* in_sizes, int n_in,
                              void* d_out, int out_size)
{
    const float* x  = (const float*)d_in[0];
    const float* Wa = (const float*)d_in[1];
    const float* Wb = (const float*)d_in[2];
    const float* Wu = (const float*)d_in[3];
    const float* bu = (const float*)d_in[4];
    const float* Wr = (const float*)d_in[5];
    float* out = (float*)d_out;

    dim3 t(256);
    gemm_nt_3  <<<dim3(F / TBN, MROWS / TBM, 3), t>>>(x, Wa, Wb, Wu, bu);
    dot_ab     <<<MROWS / 8, 256>>>();
    gemm_tn_M  <<<dim3(F / BN, F / BM, BATCH), t>>>();
    gemm_nn_att<<<dim3(F / TBN, MROWS / TBM), t>>>();
    gemm_nt_out<<<dim3(F / TBN, MROWS / TBM), t>>>(Wr, x, out);
}

// round 11
// speedup vs baseline: 2.3547x; 1.9660x over previous
#include <cuda_runtime.h>
#include <cstdint>

// Problem constants
#define BATCH 16
#define SEQ   1024
#define F     256
#define MROWS (BATCH * SEQ)   // 16384

// Tile config
#define BM  128
#define BN  128
#define BK  32
#define BKP 36    // padded row stride (floats): bank = (4*row + k) % 32 -> conflict-free frags

// -------- scratch (no allocation allowed; __device__ globals) --------
__device__ float g_alpha[MROWS * F];
__device__ float g_beta [MROWS * F];
__device__ float g_unary[MROWS * F];
__device__ float g_att  [MROWS * F];
__device__ float g_Mt   [BATCH * F * F];   // Mt[b][f][h] = sum_n unary[b,n,f]*beta[b,n,h]
__device__ float g_d    [MROWS];

// fp32 -> tf32 bits (round-to-nearest)
__device__ __forceinline__ uint32_t tf32b(float x) {
    uint32_t r;
    asm("cvt.rna.tf32.f32 %0, %1;" : "=r"(r) : "f"(x));
    return r;
}

// ============================================================================
// smem tile fills. Tile layout: S[row][k], row stride BKP=36 floats.
// ============================================================================
// K-major source (k contiguous): 256 threads, coalesced float4 loads,
// conflict-free STS.128 (phase covers words 4*kq+j = 0..31).
__device__ __forceinline__ void fill_k(uint32_t* S, const float* __restrict__ src,
                                       int ld, int row0, int k0, int tid)
{
    const int kq = tid & 7;      // float4 index along k (covers 32 floats)
    const int r0 = tid >> 3;     // 0..31
#pragma unroll
    for (int i = 0; i < 4; ++i) {
        int r = r0 + i * 32;
        float4 v = *(const float4*)&src[(row0 + r) * ld + k0 + kq * 4];
        uint4 w;
        w.x = tf32b(v.x); w.y = tf32b(v.y); w.z = tf32b(v.z); w.w = tf32b(v.w);
        *(uint4*)&S[r * BKP + kq * 4] = w;
    }
}

// MN-major source transposed on the fly: S[c][k] = src[(k0+k)*ld + c0 + c].
// 256 threads: c = tid&127, k-half = (tid>>7)*16. Scalar LDG coalesced
// across lanes (consecutive c); STS.128 conflict-free.
__device__ __forceinline__ void fill_t(uint32_t* S, const float* __restrict__ src,
                                       int ld, int c0, int k0, int tid)
{
    const int c  = tid & 127;
    const int kh = (tid >> 7) * 16;
    const float* p = &src[(k0 + kh) * ld + c0 + c];
#pragma unroll
    for (int q = 0; q < 4; ++q) {
        const float* pk = p + q * 4 * ld;
        uint4 w;
        w.x = tf32b(pk[0 * ld]); w.y = tf32b(pk[1 * ld]);
        w.z = tf32b(pk[2 * ld]); w.w = tf32b(pk[3 * ld]);
        *(uint4*)&S[c * BKP + kh + q * 4] = w;
    }
}

// ============================================================================
// Warp-level tf32 MMA core: consumes one 128x128x32 smem tile pair.
// 8 warps as (wm 2) x (wn 4); warp tile 64x32 = 4x4 m16n8k8 MMAs per k-step.
// ============================================================================
__device__ __forceinline__ void mma_core(const uint32_t* __restrict__ As,
                                         const uint32_t* __restrict__ Bs,
                                         float acc[4][4][4],
                                         int wm, int wn, int gid, int tig)
{
#pragma unroll
    for (int ks = 0; ks < 4; ++ks) {
        const int kb = ks * 8 + tig;
        uint32_t a[4][4], b[4][2];
#pragma unroll
        for (int mt = 0; mt < 4; ++mt) {
            const uint32_t* p = &As[(wm * 64 + mt * 16 + gid) * BKP + kb];
            a[mt][0] = p[0];
            a[mt][1] = p[8 * BKP];
            a[mt][2] = p[4];
            a[mt][3] = p[8 * BKP + 4];
        }
#pragma unroll
        for (int nt = 0; nt < 4; ++nt) {
            const uint32_t* p = &Bs[(wn * 32 + nt * 8 + gid) * BKP + kb];
            b[nt][0] = p[0];
            b[nt][1] = p[4];
        }
#pragma unroll
        for (int mt = 0; mt < 4; ++mt)
#pragma unroll
            for (int nt = 0; nt < 4; ++nt)
                asm volatile(
                    "mma.sync.aligned.m16n8k8.row.col.f32.tf32.tf32.f32 "
                    "{%0,%1,%2,%3}, {%4,%5,%6,%7}, {%8,%9}, {%0,%1,%2,%3};"
                    : "+f"(acc[mt][nt][0]), "+f"(acc[mt][nt][1]),
                      "+f"(acc[mt][nt][2]), "+f"(acc[mt][nt][3])
                    : "r"(a[mt][0]), "r"(a[mt][1]), "r"(a[mt][2]), "r"(a[mt][3]),
                      "r"(b[nt][0]), "r"(b[nt][1]));
    }
}

// Per-thread output coords: rows r, r+8; cols c, c+1 (float2).
#define EPILOG_COORDS()                                         \
    const int r_ = m0 + wm * 64 + mt * 16 + gid;                \
    const int c_ = n0 + wn * 32 + nt * 8 + 2 * tig;

// ============================================================================
// Kernel 1: NT GEMM  O[m,g] = sum_k X[m,k]*W[g,k]  (+bias when z==2)
// grid (2, 128, 3), 256 threads.
// ============================================================================
__global__ __launch_bounds__(256, 2) void k_nt3(
    const float* __restrict__ X,
    const float* __restrict__ W0, const float* __restrict__ W1,
    const float* __restrict__ W2, const float* __restrict__ bias)
{
    __shared__ uint32_t As[BM * BKP];
    __shared__ uint32_t Bs[BN * BKP];

    const int z = blockIdx.z;
    const float* __restrict__ W = (z == 0) ? W0 : (z == 1) ? W1 : W2;
    float* __restrict__ O = (z == 0) ? g_alpha : (z == 1) ? g_beta : g_unary;

    const int tid = threadIdx.x, lane = tid & 31, wid = tid >> 5;
    const int wm = wid & 1, wn = wid >> 1;
    const int gid = lane >> 2, tig = lane & 3;
    const int m0 = blockIdx.y * BM, n0 = blockIdx.x * BN;

    float acc[4][4][4] = {};

    for (int k0 = 0; k0 < F; k0 += BK) {
        fill_k(As, X, F, m0, k0, tid);
        fill_k(Bs, W, F, n0, k0, tid);
        __syncthreads();
        mma_core(As, Bs, acc, wm, wn, gid, tig);
        __syncthreads();
    }

#pragma unroll
    for (int mt = 0; mt < 4; ++mt)
#pragma unroll
        for (int nt = 0; nt < 4; ++nt) {
            EPILOG_COORDS()
            float2 b2 = make_float2(0.f, 0.f);
            if (z == 2) b2 = *(const float2*)&bias[c_];
            float2 o0, o1;
            o0.x = acc[mt][nt][0] + b2.x; o0.y = acc[mt][nt][1] + b2.y;
            o1.x = acc[mt][nt][2] + b2.x; o1.y = acc[mt][nt][3] + b2.y;
            *(float2*)&O[r_ * F + c_]       = o0;
            *(float2*)&O[(r_ + 8) * F + c_] = o1;
        }
}

// ============================================================================
// Kernel 2: per-row dot  d[m] = alpha[m,:].beta[m,:]  (fp32, one warp per row)
// ============================================================================
__global__ __launch_bounds__(256) void dot_ab()
{
    int row = blockIdx.x * 8 + (threadIdx.x >> 5);
    int lane = threadIdx.x & 31;
    const float4* a = (const float4*)&g_alpha[row * F];
    const float4* b = (const float4*)&g_beta[row * F];
    float s = 0.f;
#pragma unroll
    for (int i = lane; i < F / 4; i += 32) {
        float4 av = a[i], bv = b[i];
        s += av.x * bv.x + av.y * bv.y + av.z * bv.z + av.w * bv.w;
    }
#pragma unroll
    for (int off = 16; off > 0; off >>= 1)
        s += __shfl_xor_sync(0xffffffffu, s, off);
    if (lane == 0) g_d[row] = s;
}

// ============================================================================
// Kernel 3: per-batch TN GEMM  Mt[f,h] = sum_n unary[b,n,f]*beta[b,n,h]
// grid (2, 2, 16). Both operands MN-major -> transposed fills. K = SEQ.
// ============================================================================
__global__ __launch_bounds__(256, 2) void k_tnM()
{
    __shared__ uint32_t As[BM * BKP];
    __shared__ uint32_t Bs[BN * BKP];

    const int b = blockIdx.z;
    const float* __restrict__ U  = g_unary + b * SEQ * F;
    const float* __restrict__ Bt = g_beta  + b * SEQ * F;
    float* __restrict__ O = g_Mt + b * F * F;

    const int tid = threadIdx.x, lane = tid & 31, wid = tid >> 5;
    const int wm = wid & 1, wn = wid >> 1;
    const int gid = lane >> 2, tig = lane & 3;
    const int m0 = blockIdx.y * BM, n0 = blockIdx.x * BN;   // m0 = f, n0 = h

    float acc[4][4][4] = {};

    for (int k0 = 0; k0 < SEQ; k0 += BK) {
        fill_t(As, U,  F, m0, k0, tid);
        fill_t(Bs, Bt, F, n0, k0, tid);
        __syncthreads();
        mma_core(As, Bs, acc, wm, wn, gid, tig);
        __syncthreads();
    }

#pragma unroll
    for (int mt = 0; mt < 4; ++mt)
#pragma unroll
        for (int nt = 0; nt < 4; ++nt) {
            EPILOG_COORDS()
            *(float2*)&O[r_ * F + c_]       = make_float2(acc[mt][nt][0], acc[mt][nt][1]);
            *(float2*)&O[(r_ + 8) * F + c_] = make_float2(acc[mt][nt][2], acc[mt][nt][3]);
        }
}

// ============================================================================
// Kernel 4: NN GEMM  att[m,f] = (sum_h alpha[m,h]*Mt[f,h] - d[m]*u[m,f])/SEQ
// grid (2, 128). Both fills K-major (Mt stored transposed for this).
// ============================================================================
__global__ __launch_bounds__(256, 2) void k_att()
{
    __shared__ uint32_t As[BM * BKP];
    __shared__ uint32_t Bs[BN * BKP];

    const int tid = threadIdx.x, lane = tid & 31, wid = tid >> 5;
    const int wm = wid & 1, wn = wid >> 1;
    const int gid = lane >> 2, tig = lane & 3;
    const int m0 = blockIdx.y * BM, n0 = blockIdx.x * BN;
    const int b = m0 >> 10;
    const float* __restrict__ Mtb = g_Mt + b * F * F;

    float acc[4][4][4] = {};

    for (int k0 = 0; k0 < F; k0 += BK) {
        fill_k(As, g_alpha, F, m0, k0, tid);
        fill_k(Bs, Mtb,     F, n0, k0, tid);
        __syncthreads();
        mma_core(As, Bs, acc, wm, wn, gid, tig);
        __syncthreads();
    }

    const float invN = 1.0f / (float)SEQ;
#pragma unroll
    for (int mt = 0; mt < 4; ++mt)
#pragma unroll
        for (int nt = 0; nt < 4; ++nt) {
            EPILOG_COORDS()
            float d0 = g_d[r_], d1 = g_d[r_ + 8];
            float2 u0 = *(const float2*)&g_unary[r_ * F + c_];
            float2 u1 = *(const float2*)&g_unary[(r_ + 8) * F + c_];
            float2 o0, o1;
            o0.x = (acc[mt][nt][0] - d0 * u0.x) * invN;
            o0.y = (acc[mt][nt][1] - d0 * u0.y) * invN;
            o1.x = (acc[mt][nt][2] - d1 * u1.x) * invN;
            o1.y = (acc[mt][nt][3] - d1 * u1.y) * invN;
            *(float2*)&g_att[r_ * F + c_]       = o0;
            *(float2*)&g_att[(r_ + 8) * F + c_] = o1;
        }
}

// ============================================================================
// Kernel 5: NT GEMM + residual  out[m,g] = sum_f att[m,f]*W_r[g,f] + x[m,g]
// grid (2, 128).
// ============================================================================
__global__ __launch_bounds__(256, 2) void k_out(
    const float* __restrict__ Wr, const float* __restrict__ X,
    float* __restrict__ out)
{
    __shared__ uint32_t As[BM * BKP];
    __shared__ uint32_t Bs[BN * BKP];

    const int tid = threadIdx.x, lane = tid & 31, wid = tid >> 5;
    const int wm = wid & 1, wn = wid >> 1;
    const int gid = lane >> 2, tig = lane & 3;
    const int m0 = blockIdx.y * BM, n0 = blockIdx.x * BN;

    float acc[4][4][4] = {};

    for (int k0 = 0; k0 < F; k0 += BK) {
        fill_k(As, g_att, F, m0, k0, tid);
        fill_k(Bs, Wr,    F, n0, k0, tid);
        __syncthreads();
        mma_core(As, Bs, acc, wm, wn, gid, tig);
        __syncthreads();
    }

#pragma unroll
    for (int mt = 0; mt < 4; ++mt)
#pragma unroll
        for (int nt = 0; nt < 4; ++nt) {
            EPILOG_COORDS()
            float2 x0 = *(const float2*)&X[r_ * F + c_];
            float2 x1 = *(const float2*)&X[(r_ + 8) * F + c_];
            float2 o0, o1;
            o0.x = acc[mt][nt][0] + x0.x; o0.y = acc[mt][nt][1] + x0.y;
            o1.x = acc[mt][nt][2] + x1.x; o1.y = acc[mt][nt][3] + x1.y;
            *(float2*)&out[r_ * F + c_]       = o0;
            *(float2*)&out[(r_ + 8) * F + c_] = o1;
        }
}

// ============================================================================
// Launch
// ============================================================================
extern "C" void kernel_launch(void* const* d_in, const int* in_sizes, int n_in,
                              void* d_out, int out_size)
{
    const float* x  = (const float*)d_in[0];
    const float* Wa = (const float*)d_in[1];
    const float* Wb = (const float*)d_in[2];
    const float* Wu = (const float*)d_in[3];
    const float* bu = (const float*)d_in[4];
    const float* Wr = (const float*)d_in[5];
    float* out = (float*)d_out;

    k_nt3 <<<dim3(F / BN, MROWS / BM, 3), 256>>>(x, Wa, Wb, Wu, bu);
    dot_ab<<<MROWS / 8, 256>>>();
    k_tnM <<<dim3(F / BN, F / BM, BATCH), 256>>>();
    k_att <<<dim3(F / BN, MROWS / BM), 256>>>();
    k_out <<<dim3(F / BN, MROWS / BM), 256>>>(Wr, x, out);
}

// round 15
// speedup vs baseline: 2.8475x; 1.2093x over previous
#include <cuda_runtime.h>
#include <cstdint>

// Problem constants
#define BATCH 16
#define SEQ   1024
#define F     256
#define MROWS (BATCH * SEQ)   // 16384

// Tile config
#define BM  128
#define BN  128
#define BK  32
#define BKP 36    // padded row stride (floats): conflict-free frags + 16B-aligned rows
#define NSPLIT 4  // split-K for k_tnM

// -------- scratch (no allocation allowed; __device__ globals) --------
__device__ float g_alpha[MROWS * F];
__device__ float g_beta [MROWS * F];
__device__ float g_unary[MROWS * F];
__device__ float g_att  [MROWS * F];
__device__ float g_Mt   [BATCH * F * F];            // Mt[b][f][h]
__device__ float g_part [NSPLIT * BATCH * F * F];   // split-K partials
__device__ float g_d    [MROWS];

__device__ __forceinline__ uint32_t smem_u32(const void* p) {
    uint32_t a;
    asm("{ .reg .u64 t; cvta.to.shared.u64 t, %1; cvt.u32.u64 %0, t; }"
        : "=r"(a) : "l"(p));
    return a;
}

// fp32 -> tf32 bits (round-to-nearest) — used on the register fill path only
__device__ __forceinline__ uint32_t tf32b(float x) {
    uint32_t r;
    asm("cvt.rna.tf32.f32 %0, %1;" : "=r"(r) : "f"(x));
    return r;
}

// ---------------- cp.async helpers ----------------
__device__ __forceinline__ void cp16(uint32_t dst, const void* src) {
    asm volatile("cp.async.cg.shared.global [%0], [%1], 16;" :: "r"(dst), "l"(src));
}
#define CP_COMMIT() asm volatile("cp.async.commit_group;" ::: "memory")
#define CP_WAIT(N)  asm volatile("cp.async.wait_group %0;" :: "n"(N) : "memory")

// K-major async fill: 256 threads cover 128 rows x 32 floats (16B each).
__device__ __forceinline__ void fill_k_async(uint32_t Sb, const float* __restrict__ src,
                                             int ld, int row0, int k0, int tid)
{
    const int kq = tid & 7;      // 16B chunk along k
    const int r0 = tid >> 3;     // 0..31
#pragma unroll
    for (int i = 0; i < 4; ++i) {
        int r = r0 + i * 32;
        cp16(Sb + (uint32_t)(r * BKP + kq * 4) * 4u,
             src + (size_t)(row0 + r) * ld + k0 + kq * 4);
    }
}

// ---------------- transposed register fill (k_tnM) ----------------
// load: w[4] holds S[c][kh..kh+16) for c = tid&127, kh = (tid>>7)*16
__device__ __forceinline__ void ldt(uint4 w[4], const float* __restrict__ src,
                                    int ld, int c0, int k0, int tid)
{
    const int c  = tid & 127;
    const int kh = (tid >> 7) * 16;
    const float* p = &src[(size_t)(k0 + kh) * ld + c0 + c];
#pragma unroll
    for (int q = 0; q < 4; ++q) {
        const float* pk = p + q * 4 * ld;
        w[q].x = tf32b(pk[0 * ld]); w[q].y = tf32b(pk[1 * ld]);
        w[q].z = tf32b(pk[2 * ld]); w[q].w = tf32b(pk[3 * ld]);
    }
}
__device__ __forceinline__ void stt(uint32_t* S, const uint4 w[4], int tid)
{
    const int c  = tid & 127;
    const int kh = (tid >> 7) * 16;
#pragma unroll
    for (int q = 0; q < 4; ++q)
        *(uint4*)&S[c * BKP + kh + q * 4] = w[q];
}

// ============================================================================
// Warp-level tf32 MMA core: one 128x128x32 smem tile pair.
// 8 warps (wm 2 x wn 4); warp tile 64x32 = 4x4 m16n8k8 per k-step.
// ============================================================================
__device__ __forceinline__ void mma_core(const uint32_t* __restrict__ As,
                                         const uint32_t* __restrict__ Bs,
                                         float acc[4][4][4],
                                         int wm, int wn, int gid, int tig)
{
#pragma unroll
    for (int ks = 0; ks < 4; ++ks) {
        const int kb = ks * 8 + tig;
        uint32_t a[4][4], b[4][2];
#pragma unroll
        for (int mt = 0; mt < 4; ++mt) {
            const uint32_t* p = &As[(wm * 64 + mt * 16 + gid) * BKP + kb];
            a[mt][0] = p[0];
            a[mt][1] = p[8 * BKP];
            a[mt][2] = p[4];
            a[mt][3] = p[8 * BKP + 4];
        }
#pragma unroll
        for (int nt = 0; nt < 4; ++nt) {
            const uint32_t* p = &Bs[(wn * 32 + nt * 8 + gid) * BKP + kb];
            b[nt][0] = p[0];
            b[nt][1] = p[4];
        }
#pragma unroll
        for (int mt = 0; mt < 4; ++mt)
#pragma unroll
            for (int nt = 0; nt < 4; ++nt)
                asm volatile(
                    "mma.sync.aligned.m16n8k8.row.col.f32.tf32.tf32.f32 "
                    "{%0,%1,%2,%3}, {%4,%5,%6,%7}, {%8,%9}, {%0,%1,%2,%3};"
                    : "+f"(acc[mt][nt][0]), "+f"(acc[mt][nt][1]),
                      "+f"(acc[mt][nt][2]), "+f"(acc[mt][nt][3])
                    : "r"(a[mt][0]), "r"(a[mt][1]), "r"(a[mt][2]), "r"(a[mt][3]),
                      "r"(b[nt][0]), "r"(b[nt][1]));
    }
}

#define EPILOG_COORDS()                                         \
    const int r_ = m0 + wm * 64 + mt * 16 + gid;                \
    const int c_ = n0 + wn * 32 + nt * 8 + 2 * tig;

// Pipelined K-major mainloop over NK chunks (both operands K-major).
#define PIPELINED_LOOP(Asrc, Bsrc, arow0, brow0, NK)                         \
    fill_k_async(aAddr[0], Asrc, F, arow0, 0, tid);                          \
    fill_k_async(bAddr[0], Bsrc, F, brow0, 0, tid);                          \
    CP_COMMIT();                                                             \
    for (int i = 0; i < (NK); ++i) {                                         \
        if (i + 1 < (NK)) {                                                  \
            int st = (i + 1) & 1;                                            \
            fill_k_async(aAddr[st], Asrc, F, arow0, (i + 1) * BK, tid);      \
            fill_k_async(bAddr[st], Bsrc, F, brow0, (i + 1) * BK, tid);      \
            CP_COMMIT();                                                     \
            CP_WAIT(1);                                                      \
        } else {                                                             \
            CP_WAIT(0);                                                      \
        }                                                                    \
        __syncthreads();                                                     \
        mma_core(As[i & 1], Bs[i & 1], acc, wm, wn, gid, tig);               \
        __syncthreads();                                                     \
    }

// ============================================================================
// Kernel 1: NT GEMM  O[m,g] = sum_k X[m,k]*W[g,k]  (+bias when z==2)
// ============================================================================
__global__ __launch_bounds__(256, 2) void k_nt3(
    const float* __restrict__ X,
    const float* __restrict__ W0, const float* __restrict__ W1,
    const float* __restrict__ W2, const float* __restrict__ bias)
{
    __shared__ uint32_t As[2][BM * BKP];
    __shared__ uint32_t Bs[2][BN * BKP];

    const int z = blockIdx.z;
    const float* __restrict__ W = (z == 0) ? W0 : (z == 1) ? W1 : W2;
    float* __restrict__ O = (z == 0) ? g_alpha : (z == 1) ? g_beta : g_unary;

    const int tid = threadIdx.x, lane = tid & 31, wid = tid >> 5;
    const int wm = wid & 1, wn = wid >> 1;
    const int gid = lane >> 2, tig = lane & 3;
    const int m0 = blockIdx.y * BM, n0 = blockIdx.x * BN;
    const uint32_t aAddr[2] = {smem_u32(As[0]), smem_u32(As[1])};
    const uint32_t bAddr[2] = {smem_u32(Bs[0]), smem_u32(Bs[1])};

    float acc[4][4][4] = {};
    PIPELINED_LOOP(X, W, m0, n0, F / BK)

#pragma unroll
    for (int mt = 0; mt < 4; ++mt)
#pragma unroll
        for (int nt = 0; nt < 4; ++nt) {
            EPILOG_COORDS()
            float2 b2 = make_float2(0.f, 0.f);
            if (z == 2) b2 = *(const float2*)&bias[c_];
            *(float2*)&O[r_ * F + c_] =
                make_float2(acc[mt][nt][0] + b2.x, acc[mt][nt][1] + b2.y);
            *(float2*)&O[(r_ + 8) * F + c_] =
                make_float2(acc[mt][nt][2] + b2.x, acc[mt][nt][3] + b2.y);
        }
}

// ============================================================================
// Kernel 2: per-row dot  d[m] = alpha[m,:].beta[m,:]
// ============================================================================
__global__ __launch_bounds__(256) void dot_ab()
{
    int row = blockIdx.x * 8 + (threadIdx.x >> 5);
    int lane = threadIdx.x & 31;
    const float4* a = (const float4*)&g_alpha[row * F];
    const float4* b = (const float4*)&g_beta[row * F];
    float s = 0.f;
#pragma unroll
    for (int i = lane; i < F / 4; i += 32) {
        float4 av = a[i], bv = b[i];
        s += av.x * bv.x + av.y * bv.y + av.z * bv.z + av.w * bv.w;
    }
#pragma unroll
    for (int off = 16; off > 0; off >>= 1)
        s += __shfl_xor_sync(0xffffffffu, s, off);
    if (lane == 0) g_d[row] = s;
}

// ============================================================================
// Kernel 3: per-batch TN GEMM split-K:
//   part[sp][b][f][h] = sum_{n in split sp} unary[b,n,f]*beta[b,n,h]
// grid (2, 2, BATCH*NSPLIT). Register-prefetch double buffered.
// ============================================================================
__global__ __launch_bounds__(256) void k_tnM()
{
    __shared__ uint32_t As[BM * BKP];
    __shared__ uint32_t Bs[BN * BKP];

    const int b  = blockIdx.z >> 2;
    const int sp = blockIdx.z & 3;
    const float* __restrict__ U  = g_unary + (size_t)b * SEQ * F;
    const float* __restrict__ Bt = g_beta  + (size_t)b * SEQ * F;
    float* __restrict__ O = g_part + ((size_t)sp * BATCH + b) * F * F;

    const int tid = threadIdx.x, lane = tid & 31, wid = tid >> 5;
    const int wm = wid & 1, wn = wid >> 1;
    const int gid = lane >> 2, tig = lane & 3;
    const int m0 = blockIdx.y * BM, n0 = blockIdx.x * BN;   // m0 = f, n0 = h
    const int k00 = sp * (SEQ / NSPLIT);
    const int NK = (SEQ / NSPLIT) / BK;   // 8

    float acc[4][4][4] = {};
    uint4 wa[4], wb[4];
    ldt(wa, U,  F, m0, k00, tid);
    ldt(wb, Bt, F, n0, k00, tid);

    for (int i = 0; i < NK; ++i) {
        stt(As, wa, tid);
        stt(Bs, wb, tid);
        __syncthreads();
        if (i + 1 < NK) {
            ldt(wa, U,  F, m0, k00 + (i + 1) * BK, tid);
            ldt(wb, Bt, F, n0, k00 + (i + 1) * BK, tid);
        }
        mma_core(As, Bs, acc, wm, wn, gid, tig);
        __syncthreads();
    }

#pragma unroll
    for (int mt = 0; mt < 4; ++mt)
#pragma unroll
        for (int nt = 0; nt < 4; ++nt) {
            EPILOG_COORDS()
            *(float2*)&O[r_ * F + c_]       = make_float2(acc[mt][nt][0], acc[mt][nt][1]);
            *(float2*)&O[(r_ + 8) * F + c_] = make_float2(acc[mt][nt][2], acc[mt][nt][3]);
        }
}

// ============================================================================
// Kernel 3b: reduce split-K partials into g_Mt. 1M float4s of work.
// ============================================================================
__global__ __launch_bounds__(256) void k_red()
{
    const int n4 = BATCH * F * F / 4;   // float4 count per split
    int idx = blockIdx.x * 256 + threadIdx.x;
    const float4* p = (const float4*)g_part;
    float4 a = p[idx], b = p[n4 + idx], c = p[2 * n4 + idx], d = p[3 * n4 + idx];
    float4 o;
    o.x = (a.x + b.x) + (c.x + d.x);
    o.y = (a.y + b.y) + (c.y + d.y);
    o.z = (a.z + b.z) + (c.z + d.z);
    o.w = (a.w + b.w) + (c.w + d.w);
    ((float4*)g_Mt)[idx] = o;
}

// ============================================================================
// Kernel 4: NN GEMM  att[m,f] = (sum_h alpha[m,h]*Mt[f,h] - d[m]*u[m,f])/SEQ
// ============================================================================
__global__ __launch_bounds__(256, 2) void k_att()
{
    __shared__ uint32_t As[2][BM * BKP];
    __shared__ uint32_t Bs[2][BN * BKP];

    const int tid = threadIdx.x, lane = tid & 31, wid = tid >> 5;
    const int wm = wid & 1, wn = wid >> 1;
    const int gid = lane >> 2, tig = lane & 3;
    const int m0 = blockIdx.y * BM, n0 = blockIdx.x * BN;
    const int b = m0 >> 10;
    const float* __restrict__ Mtb = g_Mt + (size_t)b * F * F;
    const uint32_t aAddr[2] = {smem_u32(As[0]), smem_u32(As[1])};
    const uint32_t bAddr[2] = {smem_u32(Bs[0]), smem_u32(Bs[1])};

    float acc[4][4][4] = {};
    PIPELINED_LOOP(g_alpha, Mtb, m0, n0, F / BK)

    const float invN = 1.0f / (float)SEQ;
#pragma unroll
    for (int mt = 0; mt < 4; ++mt)
#pragma unroll
        for (int nt = 0; nt < 4; ++nt) {
            EPILOG_COORDS()
            float d0 = g_d[r_], d1 = g_d[r_ + 8];
            float2 u0 = *(const float2*)&g_unary[r_ * F + c_];
            float2 u1 = *(const float2*)&g_unary[(r_ + 8) * F + c_];
            *(float2*)&g_att[r_ * F + c_] = make_float2(
                (acc[mt][nt][0] - d0 * u0.x) * invN,
                (acc[mt][nt][1] - d0 * u0.y) * invN);
            *(float2*)&g_att[(r_ + 8) * F + c_] = make_float2(
                (acc[mt][nt][2] - d1 * u1.x) * invN,
                (acc[mt][nt][3] - d1 * u1.y) * invN);
        }
}

// ============================================================================
// Kernel 5: NT GEMM + residual  out[m,g] = sum_f att[m,f]*W_r[g,f] + x[m,g]
// ============================================================================
__global__ __launch_bounds__(256, 2) void k_out(
    const float* __restrict__ Wr, const float* __restrict__ X,
    float* __restrict__ out)
{
    __shared__ uint32_t As[2][BM * BKP];
    __shared__ uint32_t Bs[2][BN * BKP];

    const int tid = threadIdx.x, lane = tid & 31, wid = tid >> 5;
    const int wm = wid & 1, wn = wid >> 1;
    const int gid = lane >> 2, tig = lane & 3;
    const int m0 = blockIdx.y * BM, n0 = blockIdx.x * BN;
    const uint32_t aAddr[2] = {smem_u32(As[0]), smem_u32(As[1])};
    const uint32_t bAddr[2] = {smem_u32(Bs[0]), smem_u32(Bs[1])};

    float acc[4][4][4] = {};
    PIPELINED_LOOP(g_att, Wr, m0, n0, F / BK)

#pragma unroll
    for (int mt = 0; mt < 4; ++mt)
#pragma unroll
        for (int nt = 0; nt < 4; ++nt) {
            EPILOG_COORDS()
            float2 x0 = *(const float2*)&X[r_ * F + c_];
            float2 x1 = *(const float2*)&X[(r_ + 8) * F + c_];
            *(float2*)&out[r_ * F + c_] =
                make_float2(acc[mt][nt][0] + x0.x, acc[mt][nt][1] + x0.y);
            *(float2*)&out[(r_ + 8) * F + c_] =
                make_float2(acc[mt][nt][2] + x1.x, acc[mt][nt][3] + x1.y);
        }
}

// ============================================================================
// Launch
// ============================================================================
extern "C" void kernel_launch(void* const* d_in, const int* in_sizes, int n_in,
                              void* d_out, int out_size)
{
    const float* x  = (const float*)d_in[0];
    const float* Wa = (const float*)d_in[1];
    const float* Wb = (const float*)d_in[2];
    const float* Wu = (const float*)d_in[3];
    const float* bu = (const float*)d_in[4];
    const float* Wr = (const float*)d_in[5];
    float* out = (float*)d_out;

    k_nt3 <<<dim3(F / BN, MROWS / BM, 3), 256>>>(x, Wa, Wb, Wu, bu);
    dot_ab<<<MROWS / 8, 256>>>();
    k_tnM <<<dim3(F / BN, F / BM, BATCH * NSPLIT), 256>>>();
    k_red <<<BATCH * F * F / 4 / 256, 256>>>();
    k_att <<<dim3(F / BN, MROWS / BM), 256>>>();
    k_out <<<dim3(F / BN, MROWS / BM), 256>>>(Wr, x, out);
}